// round 3
// baseline (speedup 1.0000x reference)
#include <cuda_runtime.h>
#include <math.h>

#define NUSERS 500000
#define MAXN   262144
#define MAXE   4194304
#define MAXEN  (MAXE + MAXN)

// ---------------- scratch (device globals; no allocation allowed) ------------
__device__ float2 g_x   [MAXN * 32];
__device__ float2 g_x2  [MAXN * 32];
__device__ float2 g_acc [MAXN * 32];
__device__ float  g_deg [MAXN];
__device__ float  g_dinv[MAXN];
__device__ float  g_loopw[MAXN];
__device__ int    g_hasloop[MAXN];
__device__ int    g_cnt [MAXN];
__device__ int    g_s   [MAXN];
__device__ int    g_e   [MAXN];
__device__ int    g_cur [MAXN];
__device__ int    g_total;
__device__ int    g_esrc [MAXEN];
__device__ float  g_enorm[MAXEN];

// ---------------- kernels ----------------------------------------------------

__global__ void k_init(int nn) {
    int i = blockIdx.x * blockDim.x + threadIdx.x;
    if (i == 0) g_total = 0;
    if (i < nn) {
        g_deg[i] = 0.f;
        g_hasloop[i] = 0;
        g_cnt[i] = 0;
    }
}

__global__ void k_edge_stats(const int* __restrict__ row,
                             const int* __restrict__ col,
                             const float* __restrict__ w, int ee) {
    int e = blockIdx.x * blockDim.x + threadIdx.x;
    if (e >= ee) return;
    int r = row[e], c = col[e];
    if (r == c) g_hasloop[r] = 1;
    atomicAdd(&g_deg[c], w[e]);
    atomicAdd(&g_cnt[c], 1);
}

__global__ void k_finalize(int nn) {
    int i = blockIdx.x * blockDim.x + threadIdx.x;
    if (i >= nn) return;
    float lw = g_hasloop[i] ? 0.f : 1.f;
    g_loopw[i] = lw;
    float d = g_deg[i] + lw;
    g_dinv[i] = (d > 0.f) ? rsqrtf(fmaxf(d, 1e-12f)) : 0.f;
    g_cnt[i] += 1;  // appended self loop (possibly weight 0)
}

// CSR region assignment: per-block inclusive scan + one atomic for block base.
// Segments need not be globally ordered, only disjoint and contiguous per node.
__global__ void k_assign(int nn) {
    __shared__ int sh[1024];
    __shared__ int base;
    int t = threadIdx.x;
    int i = blockIdx.x * 1024 + t;
    int c = (i < nn) ? g_cnt[i] : 0;
    sh[t] = c;
    __syncthreads();
    for (int off = 1; off < 1024; off <<= 1) {
        int v = (t >= off) ? sh[t - off] : 0;
        __syncthreads();
        sh[t] += v;
        __syncthreads();
    }
    if (t == 1023) base = atomicAdd(&g_total, sh[1023]);
    __syncthreads();
    if (i < nn) {
        int start = base + sh[t] - c;   // exclusive prefix within block + base
        g_s[i]   = start;
        g_e[i]   = start + c;
        g_cur[i] = start;
    }
}

__global__ void k_scatter(const int* __restrict__ row,
                          const int* __restrict__ col,
                          const float* __restrict__ w, int ee, int nn) {
    int e = blockIdx.x * blockDim.x + threadIdx.x;
    if (e >= ee + nn) return;
    if (e < ee) {
        int r = row[e], c = col[e];
        int p = atomicAdd(&g_cur[c], 1);
        g_esrc[p]  = r;
        g_enorm[p] = g_dinv[r] * w[e] * g_dinv[c];
    } else {
        int i = e - ee;
        int p = atomicAdd(&g_cur[i], 1);
        g_esrc[p]  = i;
        float dv = g_dinv[i];
        g_enorm[p] = dv * dv * g_loopw[i];
    }
}

// node features: users -> l2norm(user_emb); items -> l2norm(proj([audio|meta]))
// one warp per node; lane handles dims (2*lane, 2*lane+1); matvec via shfl
// broadcast of the 128-dim input held in registers.
__global__ void k_feat(const int* __restrict__ batch_nodes,
                       const float* __restrict__ user_w,
                       const float* __restrict__ artist_w,
                       const float* __restrict__ album_w,
                       const float* __restrict__ audio,
                       const int* __restrict__ artist_ids,
                       const int* __restrict__ album_ids,
                       const float* __restrict__ proj_w,
                       const float* __restrict__ proj_b,
                       int nn) {
    __shared__ float Wsh[128 * 64];       // 32 KB; W[k][d] at Wsh[k*64+d]
    for (int i = threadIdx.x; i < 128 * 64; i += blockDim.x)
        Wsh[i] = proj_w[i];
    __syncthreads();

    int wid  = threadIdx.x >> 5;
    int lane = threadIdx.x & 31;
    const float2* user2   = (const float2*)user_w;
    const float2* audio2  = (const float2*)audio;
    const float2* artist2 = (const float2*)artist_w;
    const float2* album2  = (const float2*)album_w;
    const float2* pb2     = (const float2*)proj_b;
    const float2* Wsh2    = (const float2*)Wsh;

    for (int n = blockIdx.x * 8 + wid; n < nn; n += gridDim.x * 8) {
        int bn = batch_nodes[n];
        float2 o;
        if (bn < NUSERS) {
            o = user2[(size_t)bn * 32 + lane];
        } else {
            int it  = bn - NUSERS;
            int aid = artist_ids[it];
            int bid = album_ids[it];
            float2 au = audio2[(size_t)it * 32 + lane];          // in dims 2l,2l+1
            float2 ar = artist2[(size_t)aid * 32 + lane];
            float2 al = album2[(size_t)bid * 32 + lane];
            float2 me = make_float2(0.5f * (ar.x + al.x),
                                    0.5f * (ar.y + al.y));       // in dims 64+2l
            float2 s = pb2[lane];
            #pragma unroll
            for (int k = 0; k < 64; k++) {
                float iv = __shfl_sync(0xffffffffu, (k & 1) ? au.y : au.x, k >> 1);
                float2 wv = Wsh2[k * 32 + lane];
                s.x += iv * wv.x;
                s.y += iv * wv.y;
            }
            #pragma unroll
            for (int k = 0; k < 64; k++) {
                float iv = __shfl_sync(0xffffffffu, (k & 1) ? me.y : me.x, k >> 1);
                float2 wv = Wsh2[(64 + k) * 32 + lane];
                s.x += iv * wv.x;
                s.y += iv * wv.y;
            }
            o = s;
        }
        // warp l2-normalize over 64 dims
        float ss = o.x * o.x + o.y * o.y;
        #pragma unroll
        for (int off = 16; off; off >>= 1)
            ss += __shfl_xor_sync(0xffffffffu, ss, off);
        float inv = 1.0f / fmaxf(sqrtf(ss), 1e-12f);
        o.x *= inv; o.y *= inv;
        int idx = n * 32 + lane;
        g_x[idx]   = o;
        g_acc[idx] = o;
    }
}

// one propagation layer: pull-based aggregation over CSR, fused acc update.
// NOTE: ping-pong buffers selected IN DEVICE CODE — passing __device__ global
// addresses from host code silently reads the host shadow array on GB300 (ATS).
__global__ void k_prop(int sel, int nn) {
    const float2* __restrict__ xin  = sel ? g_x2 : g_x;
    float2*       __restrict__ xout = sel ? g_x  : g_x2;
    int g = blockIdx.x * blockDim.x + threadIdx.x;
    int n = g >> 5;
    int lane = g & 31;
    if (n >= nn) return;
    int s = g_s[n];
    int e = g_e[n];
    float ax = 0.f, ay = 0.f;
    int j = s;
    for (; j + 4 <= e; j += 4) {
        int   r0 = g_esrc[j],     r1 = g_esrc[j + 1];
        int   r2 = g_esrc[j + 2], r3 = g_esrc[j + 3];
        float w0 = g_enorm[j],     w1 = g_enorm[j + 1];
        float w2 = g_enorm[j + 2], w3 = g_enorm[j + 3];
        float2 v0 = xin[r0 * 32 + lane];
        float2 v1 = xin[r1 * 32 + lane];
        float2 v2 = xin[r2 * 32 + lane];
        float2 v3 = xin[r3 * 32 + lane];
        ax += w0 * v0.x + w1 * v1.x + w2 * v2.x + w3 * v3.x;
        ay += w0 * v0.y + w1 * v1.y + w2 * v2.y + w3 * v3.y;
    }
    for (; j < e; j++) {
        int r = g_esrc[j];
        float w = g_enorm[j];
        float2 v = xin[r * 32 + lane];
        ax += w * v.x;
        ay += w * v.y;
    }
    int o = n * 32 + lane;
    xout[o] = make_float2(ax, ay);
    float2 ac = g_acc[o];
    ac.x += ax; ac.y += ay;
    g_acc[o] = ac;
}

// out = l2norm(acc / 4)
__global__ void k_final(float2* __restrict__ out, int nn) {
    int g = blockIdx.x * blockDim.x + threadIdx.x;
    int n = g >> 5;
    int lane = g & 31;
    if (n >= nn) return;
    int idx = n * 32 + lane;
    float2 a = g_acc[idx];
    a.x *= 0.25f; a.y *= 0.25f;
    float ss = a.x * a.x + a.y * a.y;
    #pragma unroll
    for (int off = 16; off; off >>= 1)
        ss += __shfl_xor_sync(0xffffffffu, ss, off);
    float inv = 1.0f / fmaxf(sqrtf(ss), 1e-12f);
    a.x *= inv; a.y *= inv;
    out[idx] = a;
}

// ---------------- launch -----------------------------------------------------

extern "C" void kernel_launch(void* const* d_in, const int* in_sizes, int n_in,
                              void* d_out, int out_size) {
    const int*   batch_nodes = (const int*)  d_in[0];
    const int*   edge_index  = (const int*)  d_in[1];   // [2, E] row-major
    const float* edge_w      = (const float*)d_in[2];
    const float* user_w      = (const float*)d_in[3];
    const float* artist_w    = (const float*)d_in[4];
    const float* album_w     = (const float*)d_in[5];
    const float* audio       = (const float*)d_in[6];
    const int*   artist_ids  = (const int*)  d_in[7];
    const int*   album_ids   = (const int*)  d_in[8];
    const float* proj_w      = (const float*)d_in[9];
    const float* proj_b      = (const float*)d_in[10];
    float2*      out         = (float2*)d_out;

    const int nn = in_sizes[0];                 // N nodes (runtime)
    const int ee = in_sizes[2];                 // E edges (runtime, = len(edge_w))
    const int* row = edge_index;
    const int* col = edge_index + (in_sizes[1] - ee);  // second half of [2,E]

    k_init      <<<(nn + 255) / 256, 256>>>(nn);
    k_edge_stats<<<(ee + 255) / 256, 256>>>(row, col, edge_w, ee);
    k_finalize  <<<(nn + 255) / 256, 256>>>(nn);
    k_assign    <<<(nn + 1023) / 1024, 1024>>>(nn);
    k_scatter   <<<(ee + nn + 255) / 256, 256>>>(row, col, edge_w, ee, nn);
    k_feat      <<<1024, 256>>>(batch_nodes, user_w, artist_w, album_w, audio,
                                artist_ids, album_ids, proj_w, proj_b, nn);

    const int prop_blocks = (nn * 32 + 255) / 256;   // one warp per node
    k_prop<<<prop_blocks, 256>>>(0, nn);    // layer 1: g_x  -> g_x2
    k_prop<<<prop_blocks, 256>>>(1, nn);    // layer 2: g_x2 -> g_x
    k_prop<<<prop_blocks, 256>>>(0, nn);    // layer 3: g_x  -> g_x2

    k_final<<<prop_blocks, 256>>>(out, nn);
}

// round 4
// speedup vs baseline: 1.0673x; 1.0673x over previous
#include <cuda_runtime.h>
#include <math.h>

#define NUSERS 500000
#define MAXN   262144
#define MAXE   4194304
#define MAXEN  (MAXE + MAXN)

// ---------------- scratch (device globals; no allocation allowed) ------------
__device__ float2 g_x0  [MAXN * 32];
__device__ float2 g_x1  [MAXN * 32];
__device__ float2 g_xx2 [MAXN * 32];
__device__ float  g_deg [MAXN];
__device__ float  g_dinv[MAXN];
__device__ float  g_loopw[MAXN];
__device__ int    g_hasloop[MAXN];
__device__ int    g_cnt [MAXN];
__device__ int    g_s   [MAXN];
__device__ int    g_e   [MAXN];
__device__ int    g_cur [MAXN];
__device__ int    g_total;
__device__ int2   g_edge[MAXEN];     // (src, __float_as_int(norm))

__device__ __forceinline__ float2* xbuf(int i) {
    return (i == 0) ? g_x0 : ((i == 1) ? g_x1 : g_xx2);
}

// ---------------- kernels ----------------------------------------------------

__global__ void k_init(int nn) {
    int i = blockIdx.x * blockDim.x + threadIdx.x;
    if (i == 0) g_total = 0;
    if (i < nn) {
        g_deg[i] = 0.f;
        g_hasloop[i] = 0;
        g_cnt[i] = 0;
    }
}

__global__ void k_edge_stats(const int* __restrict__ row,
                             const int* __restrict__ col,
                             const float* __restrict__ w, int ee) {
    int e = blockIdx.x * blockDim.x + threadIdx.x;
    if (e >= ee) return;
    int r = row[e], c = col[e];
    if (r == c) g_hasloop[r] = 1;
    atomicAdd(&g_deg[c], w[e]);
    atomicAdd(&g_cnt[c], 1);
}

// fused finalize (loopw/dinv/cnt+1) + CSR region assignment:
// per-block inclusive scan + one atomic for the block base. Segments need not
// be globally ordered, only disjoint and contiguous per node.
__global__ void k_assign(int nn) {
    __shared__ int sh[1024];
    __shared__ int base;
    int t = threadIdx.x;
    int i = blockIdx.x * 1024 + t;
    int c = 0;
    if (i < nn) {
        float lw = g_hasloop[i] ? 0.f : 1.f;
        g_loopw[i] = lw;
        float d = g_deg[i] + lw;
        g_dinv[i] = (d > 0.f) ? rsqrtf(fmaxf(d, 1e-12f)) : 0.f;
        c = g_cnt[i] + 1;                 // + appended self loop
    }
    sh[t] = c;
    __syncthreads();
    for (int off = 1; off < 1024; off <<= 1) {
        int v = (t >= off) ? sh[t - off] : 0;
        __syncthreads();
        sh[t] += v;
        __syncthreads();
    }
    if (t == 1023) base = atomicAdd(&g_total, sh[1023]);
    __syncthreads();
    if (i < nn) {
        int start = base + sh[t] - c;
        g_s[i]   = start;
        g_e[i]   = start + c;
        g_cur[i] = start;
    }
}

__global__ void k_scatter(const int* __restrict__ row,
                          const int* __restrict__ col,
                          const float* __restrict__ w, int ee, int nn) {
    int e = blockIdx.x * blockDim.x + threadIdx.x;
    if (e >= ee + nn) return;
    if (e < ee) {
        int r = row[e], c = col[e];
        int p = atomicAdd(&g_cur[c], 1);
        float nm = g_dinv[r] * w[e] * g_dinv[c];
        g_edge[p] = make_int2(r, __float_as_int(nm));
    } else {
        int i = e - ee;
        int p = atomicAdd(&g_cur[i], 1);
        float dv = g_dinv[i];
        g_edge[p] = make_int2(i, __float_as_int(dv * dv * g_loopw[i]));
    }
}

// node features: users -> l2norm(user_emb); items -> l2norm(proj([audio|meta]))
// one warp per node; lane handles dims (2*lane, 2*lane+1); matvec via shfl
// broadcast of the 128-dim input held in registers. Writes x0 only.
__global__ void k_feat(const int* __restrict__ batch_nodes,
                       const float* __restrict__ user_w,
                       const float* __restrict__ artist_w,
                       const float* __restrict__ album_w,
                       const float* __restrict__ audio,
                       const int* __restrict__ artist_ids,
                       const int* __restrict__ album_ids,
                       const float* __restrict__ proj_w,
                       const float* __restrict__ proj_b,
                       int nn) {
    __shared__ float Wsh[128 * 64];       // 32 KB; W[k][d] at Wsh[k*64+d]
    for (int i = threadIdx.x; i < 128 * 64; i += blockDim.x)
        Wsh[i] = proj_w[i];
    __syncthreads();

    int wid  = threadIdx.x >> 5;
    int lane = threadIdx.x & 31;
    const float2* user2   = (const float2*)user_w;
    const float2* audio2  = (const float2*)audio;
    const float2* artist2 = (const float2*)artist_w;
    const float2* album2  = (const float2*)album_w;
    const float2* pb2     = (const float2*)proj_b;
    const float2* Wsh2    = (const float2*)Wsh;

    for (int n = blockIdx.x * 8 + wid; n < nn; n += gridDim.x * 8) {
        int bn = batch_nodes[n];
        float2 o;
        if (bn < NUSERS) {
            o = user2[(size_t)bn * 32 + lane];
        } else {
            int it  = bn - NUSERS;
            int aid = artist_ids[it];
            int bid = album_ids[it];
            float2 au = audio2[(size_t)it * 32 + lane];
            float2 ar = artist2[(size_t)aid * 32 + lane];
            float2 al = album2[(size_t)bid * 32 + lane];
            float2 me = make_float2(0.5f * (ar.x + al.x),
                                    0.5f * (ar.y + al.y));
            float2 s = pb2[lane];
            #pragma unroll
            for (int k = 0; k < 64; k++) {
                float iv = __shfl_sync(0xffffffffu, (k & 1) ? au.y : au.x, k >> 1);
                float2 wv = Wsh2[k * 32 + lane];
                s.x += iv * wv.x;
                s.y += iv * wv.y;
            }
            #pragma unroll
            for (int k = 0; k < 64; k++) {
                float iv = __shfl_sync(0xffffffffu, (k & 1) ? me.y : me.x, k >> 1);
                float2 wv = Wsh2[(64 + k) * 32 + lane];
                s.x += iv * wv.x;
                s.y += iv * wv.y;
            }
            o = s;
        }
        float ss = o.x * o.x + o.y * o.y;
        #pragma unroll
        for (int off = 16; off; off >>= 1)
            ss += __shfl_xor_sync(0xffffffffu, ss, off);
        float inv = 1.0f / fmaxf(sqrtf(ss), 1e-12f);
        o.x *= inv; o.y *= inv;
        g_x0[n * 32 + lane] = o;
    }
}

// one propagation layer: pull-based aggregation over CSR.
// Edge records loaded coalesced (32/warp) then shfl-broadcast per edge.
// last!=0: fuse final l2norm((x0+x1+x2+x3)/4) and write d_out directly.
__global__ void k_prop(int si, int so, int last, int nn,
                       float2* __restrict__ out) {
    const float2* __restrict__ xin = xbuf(si);
    int g = blockIdx.x * blockDim.x + threadIdx.x;
    int n = g >> 5;
    int lane = g & 31;
    if (n >= nn) return;
    int s = g_s[n];
    int e = g_e[n];
    float ax = 0.f, ay = 0.f;
    for (int base = s; base < e; base += 32) {
        int rem = e - base;
        int cnt = rem < 32 ? rem : 32;
        int2 ed = make_int2(0, 0);
        if (lane < cnt) ed = g_edge[base + lane];
        #pragma unroll 4
        for (int j = 0; j < cnt; j++) {
            int   r = __shfl_sync(0xffffffffu, ed.x, j);
            float w = __int_as_float(__shfl_sync(0xffffffffu, ed.y, j));
            float2 v = xin[r * 32 + lane];
            ax += w * v.x;
            ay += w * v.y;
        }
    }
    int o = n * 32 + lane;
    if (!last) {
        xbuf(so)[o] = make_float2(ax, ay);
    } else {
        float2 x0 = g_x0[o];
        float2 x1 = g_x1[o];
        float2 x2 = xin[o];     // xin == g_xx2 on the last layer
        float fx = (x0.x + x1.x + x2.x + ax) * 0.25f;
        float fy = (x0.y + x1.y + x2.y + ay) * 0.25f;
        float ss = fx * fx + fy * fy;
        #pragma unroll
        for (int off = 16; off; off >>= 1)
            ss += __shfl_xor_sync(0xffffffffu, ss, off);
        float inv = 1.0f / fmaxf(sqrtf(ss), 1e-12f);
        out[o] = make_float2(fx * inv, fy * inv);
    }
}

// ---------------- launch -----------------------------------------------------

extern "C" void kernel_launch(void* const* d_in, const int* in_sizes, int n_in,
                              void* d_out, int out_size) {
    const int*   batch_nodes = (const int*)  d_in[0];
    const int*   edge_index  = (const int*)  d_in[1];   // [2, E] row-major
    const float* edge_w      = (const float*)d_in[2];
    const float* user_w      = (const float*)d_in[3];
    const float* artist_w    = (const float*)d_in[4];
    const float* album_w     = (const float*)d_in[5];
    const float* audio       = (const float*)d_in[6];
    const int*   artist_ids  = (const int*)  d_in[7];
    const int*   album_ids   = (const int*)  d_in[8];
    const float* proj_w      = (const float*)d_in[9];
    const float* proj_b      = (const float*)d_in[10];
    float2*      out         = (float2*)d_out;

    const int nn = in_sizes[0];                 // N nodes (runtime)
    const int ee = in_sizes[2];                 // E edges (runtime, = len(edge_w))
    const int* row = edge_index;
    const int* col = edge_index + (in_sizes[1] - ee);  // second half of [2,E]

    k_init      <<<(nn + 255) / 256, 256>>>(nn);
    k_edge_stats<<<(ee + 255) / 256, 256>>>(row, col, edge_w, ee);
    k_assign    <<<(nn + 1023) / 1024, 1024>>>(nn);
    k_scatter   <<<(ee + nn + 255) / 256, 256>>>(row, col, edge_w, ee, nn);
    k_feat      <<<1024, 256>>>(batch_nodes, user_w, artist_w, album_w, audio,
                                artist_ids, album_ids, proj_w, proj_b, nn);

    const int prop_blocks = (nn * 32 + 255) / 256;   // one warp per node
    k_prop<<<prop_blocks, 256>>>(0, 1, 0, nn, out);  // x0 -> x1
    k_prop<<<prop_blocks, 256>>>(1, 2, 0, nn, out);  // x1 -> x2
    k_prop<<<prop_blocks, 256>>>(2, 0, 1, nn, out);  // x2 -> out (fused final)
}

// round 5
// speedup vs baseline: 1.1216x; 1.0510x over previous
#include <cuda_runtime.h>
#include <cuda_fp16.h>
#include <math.h>

#define NUSERS 500000
#define MAXN   262144
#define MAXE   4194304
#define MAXEN  (MAXE + MAXN)

// ---------------- scratch (device globals; no allocation allowed) ------------
__device__ __half2 g_h0 [MAXN * 32];   // layer features, 2 dims per lane (fp16)
__device__ __half2 g_h1 [MAXN * 32];
__device__ __half2 g_h2 [MAXN * 32];
__device__ float   g_deg [MAXN];
__device__ float   g_dinv[MAXN];
__device__ float   g_loopw[MAXN];
__device__ int     g_hasloop[MAXN];
__device__ int     g_cnt [MAXN];
__device__ int     g_s   [MAXN];
__device__ int     g_e   [MAXN];
__device__ int     g_cur [MAXN];
__device__ int     g_total;
__device__ int2    g_edge[MAXEN];      // (src, __float_as_int(norm))

__device__ __forceinline__ __half2* hbuf(int i) {
    return (i == 0) ? g_h0 : ((i == 1) ? g_h1 : g_h2);
}

// ---------------- kernels ----------------------------------------------------

__global__ void k_init(int nn) {
    int i = blockIdx.x * blockDim.x + threadIdx.x;
    if (i == 0) g_total = 0;
    if (i < nn) {
        g_deg[i] = 0.f;
        g_hasloop[i] = 0;
        g_cnt[i] = 0;
    }
}

__global__ void k_edge_stats(const int* __restrict__ row,
                             const int* __restrict__ col,
                             const float* __restrict__ w, int ee) {
    int e = blockIdx.x * blockDim.x + threadIdx.x;
    if (e >= ee) return;
    int r = row[e], c = col[e];
    if (r == c) g_hasloop[r] = 1;
    atomicAdd(&g_deg[c], w[e]);
    atomicAdd(&g_cnt[c], 1);
}

// fused finalize (loopw/dinv) + CSR region assignment:
// per-block inclusive scan + one atomic for the block base. Segments need not
// be globally ordered, only disjoint and contiguous per node.
__global__ void k_assign(int nn) {
    __shared__ int sh[1024];
    __shared__ int base;
    int t = threadIdx.x;
    int i = blockIdx.x * 1024 + t;
    int c = 0;
    if (i < nn) {
        float lw = g_hasloop[i] ? 0.f : 1.f;
        g_loopw[i] = lw;
        float d = g_deg[i] + lw;
        g_dinv[i] = (d > 0.f) ? rsqrtf(fmaxf(d, 1e-12f)) : 0.f;
        c = g_cnt[i] + 1;                 // + appended self loop
    }
    sh[t] = c;
    __syncthreads();
    for (int off = 1; off < 1024; off <<= 1) {
        int v = (t >= off) ? sh[t - off] : 0;
        __syncthreads();
        sh[t] += v;
        __syncthreads();
    }
    if (t == 1023) base = atomicAdd(&g_total, sh[1023]);
    __syncthreads();
    if (i < nn) {
        int start = base + sh[t] - c;
        g_s[i]   = start;
        g_e[i]   = start + c;
        g_cur[i] = start;
    }
}

__global__ void k_scatter(const int* __restrict__ row,
                          const int* __restrict__ col,
                          const float* __restrict__ w, int ee, int nn) {
    int e = blockIdx.x * blockDim.x + threadIdx.x;
    if (e >= ee + nn) return;
    if (e < ee) {
        int r = row[e], c = col[e];
        int p = atomicAdd(&g_cur[c], 1);
        float nm = g_dinv[r] * w[e] * g_dinv[c];
        g_edge[p] = make_int2(r, __float_as_int(nm));
    } else {
        int i = e - ee;
        int p = atomicAdd(&g_cur[i], 1);
        float dv = g_dinv[i];
        g_edge[p] = make_int2(i, __float_as_int(dv * dv * g_loopw[i]));
    }
}

// node features: users -> l2norm(user_emb); items -> l2norm(proj([audio|meta]))
// one warp per node; lane handles dims (2*lane, 2*lane+1); matvec via shfl
// broadcast of the 128-dim input held in registers. Writes x0 (fp16).
__global__ void k_feat(const int* __restrict__ batch_nodes,
                       const float* __restrict__ user_w,
                       const float* __restrict__ artist_w,
                       const float* __restrict__ album_w,
                       const float* __restrict__ audio,
                       const int* __restrict__ artist_ids,
                       const int* __restrict__ album_ids,
                       const float* __restrict__ proj_w,
                       const float* __restrict__ proj_b,
                       int nn) {
    __shared__ float Wsh[128 * 64];       // 32 KB; W[k][d] at Wsh[k*64+d]
    for (int i = threadIdx.x; i < 128 * 64; i += blockDim.x)
        Wsh[i] = proj_w[i];
    __syncthreads();

    int wid  = threadIdx.x >> 5;
    int lane = threadIdx.x & 31;
    const float2* user2   = (const float2*)user_w;
    const float2* audio2  = (const float2*)audio;
    const float2* artist2 = (const float2*)artist_w;
    const float2* album2  = (const float2*)album_w;
    const float2* pb2     = (const float2*)proj_b;
    const float2* Wsh2    = (const float2*)Wsh;

    for (int n = blockIdx.x * 8 + wid; n < nn; n += gridDim.x * 8) {
        int bn = batch_nodes[n];
        float2 o;
        if (bn < NUSERS) {
            o = user2[(size_t)bn * 32 + lane];
        } else {
            int it  = bn - NUSERS;
            int aid = artist_ids[it];
            int bid = album_ids[it];
            float2 au = audio2[(size_t)it * 32 + lane];
            float2 ar = artist2[(size_t)aid * 32 + lane];
            float2 al = album2[(size_t)bid * 32 + lane];
            float2 me = make_float2(0.5f * (ar.x + al.x),
                                    0.5f * (ar.y + al.y));
            float2 s = pb2[lane];
            #pragma unroll
            for (int k = 0; k < 64; k++) {
                float iv = __shfl_sync(0xffffffffu, (k & 1) ? au.y : au.x, k >> 1);
                float2 wv = Wsh2[k * 32 + lane];
                s.x += iv * wv.x;
                s.y += iv * wv.y;
            }
            #pragma unroll
            for (int k = 0; k < 64; k++) {
                float iv = __shfl_sync(0xffffffffu, (k & 1) ? me.y : me.x, k >> 1);
                float2 wv = Wsh2[(64 + k) * 32 + lane];
                s.x += iv * wv.x;
                s.y += iv * wv.y;
            }
            o = s;
        }
        float ss = o.x * o.x + o.y * o.y;
        #pragma unroll
        for (int off = 16; off; off >>= 1)
            ss += __shfl_xor_sync(0xffffffffu, ss, off);
        float inv = 1.0f / fmaxf(sqrtf(ss), 1e-12f);
        o.x *= inv; o.y *= inv;
        g_h0[n * 32 + lane] = __float22half2_rn(o);
    }
}

// one propagation layer: pull-based aggregation over CSR.
// Features gathered as half2 (4B/lane), accumulated in fp32.
// Edge records loaded coalesced (32/warp) then shfl-broadcast per edge.
// last!=0: fuse final l2norm((x0+x1+x2+x3)/4) and write d_out (fp32).
__global__ void k_prop(int si, int so, int last, int nn,
                       float2* __restrict__ out) {
    const __half2* __restrict__ xin = hbuf(si);
    int g = blockIdx.x * blockDim.x + threadIdx.x;
    int n = g >> 5;
    int lane = g & 31;
    if (n >= nn) return;
    int s = g_s[n];
    int e = g_e[n];
    float ax = 0.f, ay = 0.f;
    for (int base = s; base < e; base += 32) {
        int rem = e - base;
        int cnt = rem < 32 ? rem : 32;
        int2 ed = make_int2(0, 0);
        if (lane < cnt) ed = g_edge[base + lane];
        #pragma unroll 4
        for (int j = 0; j < cnt; j++) {
            int   r = __shfl_sync(0xffffffffu, ed.x, j);
            float w = __int_as_float(__shfl_sync(0xffffffffu, ed.y, j));
            float2 v = __half22float2(xin[r * 32 + lane]);
            ax += w * v.x;
            ay += w * v.y;
        }
    }
    int o = n * 32 + lane;
    if (!last) {
        hbuf(so)[o] = __float22half2_rn(make_float2(ax, ay));
    } else {
        float2 x0 = __half22float2(g_h0[o]);
        float2 x1 = __half22float2(g_h1[o]);
        float2 x2 = __half22float2(xin[o]);   // xin == g_h2 on the last layer
        float fx = (x0.x + x1.x + x2.x + ax) * 0.25f;
        float fy = (x0.y + x1.y + x2.y + ay) * 0.25f;
        float ss = fx * fx + fy * fy;
        #pragma unroll
        for (int off = 16; off; off >>= 1)
            ss += __shfl_xor_sync(0xffffffffu, ss, off);
        float inv = 1.0f / fmaxf(sqrtf(ss), 1e-12f);
        out[o] = make_float2(fx * inv, fy * inv);
    }
}

// ---------------- launch -----------------------------------------------------

extern "C" void kernel_launch(void* const* d_in, const int* in_sizes, int n_in,
                              void* d_out, int out_size) {
    const int*   batch_nodes = (const int*)  d_in[0];
    const int*   edge_index  = (const int*)  d_in[1];   // [2, E] row-major
    const float* edge_w      = (const float*)d_in[2];
    const float* user_w      = (const float*)d_in[3];
    const float* artist_w    = (const float*)d_in[4];
    const float* album_w     = (const float*)d_in[5];
    const float* audio       = (const float*)d_in[6];
    const int*   artist_ids  = (const int*)  d_in[7];
    const int*   album_ids   = (const int*)  d_in[8];
    const float* proj_w      = (const float*)d_in[9];
    const float* proj_b      = (const float*)d_in[10];
    float2*      out         = (float2*)d_out;

    const int nn = in_sizes[0];                 // N nodes (runtime)
    const int ee = in_sizes[2];                 // E edges (runtime, = len(edge_w))
    const int* row = edge_index;
    const int* col = edge_index + (in_sizes[1] - ee);  // second half of [2,E]

    k_init      <<<(nn + 255) / 256, 256>>>(nn);
    k_edge_stats<<<(ee + 255) / 256, 256>>>(row, col, edge_w, ee);
    k_assign    <<<(nn + 1023) / 1024, 1024>>>(nn);
    k_scatter   <<<(ee + nn + 255) / 256, 256>>>(row, col, edge_w, ee, nn);
    k_feat      <<<1024, 256>>>(batch_nodes, user_w, artist_w, album_w, audio,
                                artist_ids, album_ids, proj_w, proj_b, nn);

    const int prop_blocks = (nn * 32 + 255) / 256;   // one warp per node
    k_prop<<<prop_blocks, 256>>>(0, 1, 0, nn, out);  // h0 -> h1
    k_prop<<<prop_blocks, 256>>>(1, 2, 0, nn, out);  // h1 -> h2
    k_prop<<<prop_blocks, 256>>>(2, 0, 1, nn, out);  // h2 -> out (fused final)
}

// round 6
// speedup vs baseline: 1.1276x; 1.0053x over previous
#include <cuda_runtime.h>
#include <cuda_fp16.h>
#include <math.h>

#define NUSERS 500000
#define MAXN   262144
#define MAXE   4194304
#define MAXEN  (MAXE + MAXN)

// ---------------- scratch (device globals; no allocation allowed) ------------
__device__ __half2 g_h0 [MAXN * 32];   // features: row n = 64 halfs (128B)
__device__ __half2 g_h1 [MAXN * 32];
__device__ __half2 g_h2 [MAXN * 32];
__device__ float   g_dinv [MAXN];
__device__ float   g_loopw[MAXN];
__device__ int     g_s   [MAXN];
__device__ int     g_e   [MAXN];
__device__ int     g_cur [MAXN];
// packed zero-init blob: [deg(fp32) nn][hasloop nn][cnt nn][total]
__device__ int     g_blob[3 * MAXN + 1];
__device__ int2    g_edge[MAXEN];      // (src, __float_as_int(norm))

__device__ __forceinline__ __half2* hbuf(int i) {
    return (i == 0) ? g_h0 : ((i == 1) ? g_h1 : g_h2);
}

// ---------------- kernels ----------------------------------------------------

__global__ void k_edge_stats(const int* __restrict__ row,
                             const int* __restrict__ col,
                             const float* __restrict__ w, int ee, int nn) {
    int e = blockIdx.x * blockDim.x + threadIdx.x;
    if (e >= ee) return;
    float* deg     = (float*)g_blob;
    int*   hasloop = g_blob + nn;
    int*   cnt     = g_blob + 2 * nn;
    int r = row[e], c = col[e];
    if (r == c) hasloop[r] = 1;
    atomicAdd(&deg[c], w[e]);
    atomicAdd(&cnt[c], 1);
}

// fused finalize (loopw/dinv) + CSR region assignment:
// per-block inclusive scan + one atomic for the block base.
__global__ void k_assign(int nn) {
    __shared__ int sh[1024];
    __shared__ int base;
    const float* deg     = (const float*)g_blob;
    const int*   hasloop = g_blob + nn;
    const int*   cnt     = g_blob + 2 * nn;
    int*         total   = g_blob + 3 * nn;
    int t = threadIdx.x;
    int i = blockIdx.x * 1024 + t;
    int c = 0;
    if (i < nn) {
        float lw = hasloop[i] ? 0.f : 1.f;
        g_loopw[i] = lw;
        float d = deg[i] + lw;
        g_dinv[i] = (d > 0.f) ? rsqrtf(fmaxf(d, 1e-12f)) : 0.f;
        c = cnt[i] + 1;                   // + appended self loop
    }
    sh[t] = c;
    __syncthreads();
    for (int off = 1; off < 1024; off <<= 1) {
        int v = (t >= off) ? sh[t - off] : 0;
        __syncthreads();
        sh[t] += v;
        __syncthreads();
    }
    if (t == 1023) base = atomicAdd(total, sh[1023]);
    __syncthreads();
    if (i < nn) {
        int start = base + sh[t] - c;
        g_s[i]   = start;
        g_e[i]   = start + c;
        g_cur[i] = start;
    }
}

// merged kernel: blocks [0, sb) scatter CSR edges; blocks [sb, sb+1024) build
// node features. Both only depend on k_assign.
__global__ void k_build(const int* __restrict__ row,
                        const int* __restrict__ col,
                        const float* __restrict__ w,
                        const int* __restrict__ batch_nodes,
                        const float* __restrict__ user_w,
                        const float* __restrict__ artist_w,
                        const float* __restrict__ album_w,
                        const float* __restrict__ audio,
                        const int* __restrict__ artist_ids,
                        const int* __restrict__ album_ids,
                        const float* __restrict__ proj_w,
                        const float* __restrict__ proj_b,
                        int ee, int nn, int sb) {
    __shared__ float Wsh[128 * 64];       // 32 KB; used by feat role only

    if (blockIdx.x < sb) {
        // ----- scatter role -----
        int e = blockIdx.x * blockDim.x + threadIdx.x;
        if (e >= ee + nn) return;
        if (e < ee) {
            int r = row[e], c = col[e];
            int p = atomicAdd(&g_cur[c], 1);
            float nm = g_dinv[r] * w[e] * g_dinv[c];
            g_edge[p] = make_int2(r, __float_as_int(nm));
        } else {
            int i = e - ee;
            int p = atomicAdd(&g_cur[i], 1);
            float dv = g_dinv[i];
            g_edge[p] = make_int2(i, __float_as_int(dv * dv * g_loopw[i]));
        }
        return;
    }

    // ----- feature role -----
    int fbid = blockIdx.x - sb;
    for (int i = threadIdx.x; i < 128 * 64; i += blockDim.x)
        Wsh[i] = proj_w[i];
    __syncthreads();

    int wid  = threadIdx.x >> 5;
    int lane = threadIdx.x & 31;
    const float2* user2   = (const float2*)user_w;
    const float2* audio2  = (const float2*)audio;
    const float2* artist2 = (const float2*)artist_w;
    const float2* album2  = (const float2*)album_w;
    const float2* pb2     = (const float2*)proj_b;
    const float2* Wsh2    = (const float2*)Wsh;

    for (int n = fbid * 8 + wid; n < nn; n += 1024 * 8) {
        int bn = batch_nodes[n];
        float2 o;
        if (bn < NUSERS) {
            o = user2[(size_t)bn * 32 + lane];
        } else {
            int it  = bn - NUSERS;
            int aid = artist_ids[it];
            int bid = album_ids[it];
            float2 au = audio2[(size_t)it * 32 + lane];
            float2 ar = artist2[(size_t)aid * 32 + lane];
            float2 al = album2[(size_t)bid * 32 + lane];
            float2 me = make_float2(0.5f * (ar.x + al.x),
                                    0.5f * (ar.y + al.y));
            float2 s = pb2[lane];
            #pragma unroll
            for (int k = 0; k < 64; k++) {
                float iv = __shfl_sync(0xffffffffu, (k & 1) ? au.y : au.x, k >> 1);
                float2 wv = Wsh2[k * 32 + lane];
                s.x += iv * wv.x;
                s.y += iv * wv.y;
            }
            #pragma unroll
            for (int k = 0; k < 64; k++) {
                float iv = __shfl_sync(0xffffffffu, (k & 1) ? me.y : me.x, k >> 1);
                float2 wv = Wsh2[(64 + k) * 32 + lane];
                s.x += iv * wv.x;
                s.y += iv * wv.y;
            }
            o = s;
        }
        float ss = o.x * o.x + o.y * o.y;
        #pragma unroll
        for (int off = 16; off; off >>= 1)
            ss += __shfl_xor_sync(0xffffffffu, ss, off);
        float inv = 1.0f / fmaxf(sqrtf(ss), 1e-12f);
        o.x *= inv; o.y *= inv;
        g_h0[(size_t)n * 32 + lane] = __float22half2_rn(o);
    }
}

// propagation layer v2: warp per node; 4 edge-groups of 8 lanes; each lane
// gathers 16B (8 fp16 dims) per edge -> 4 edges per iteration, 1 LDG + 2 SHFL.
// fp32 accumulation; cross-group shfl reduce; last layer fuses final l2norm.
__global__ void k_prop(int si, int so, int last, int nn,
                       float2* __restrict__ out) {
    const __half2* __restrict__ xin = hbuf(si);
    int g = blockIdx.x * blockDim.x + threadIdx.x;
    int n = g >> 5;
    if (n >= nn) return;
    int lane = threadIdx.x & 31;
    int grp  = lane >> 3;     // edge group 0..3
    int li   = lane & 7;      // lane within group (covers dims 8li..8li+7)

    int s = g_s[n];
    int e = g_e[n];
    float4 a0 = make_float4(0.f, 0.f, 0.f, 0.f);
    float4 a1 = make_float4(0.f, 0.f, 0.f, 0.f);

    for (int base = s; base < e; base += 32) {
        int cnt = e - base; if (cnt > 32) cnt = 32;
        int2 ed = make_int2(0, 0);
        if (lane < cnt) ed = g_edge[base + lane];
        int nt = (cnt + 3) >> 2;
        #pragma unroll 2
        for (int t = 0; t < nt; t++) {
            int src = t * 4 + grp;
            int   r = __shfl_sync(0xffffffffu, ed.x, src);
            float wgt = __int_as_float(__shfl_sync(0xffffffffu, ed.y, src));
            int4 hv = ((const int4*)(xin + (size_t)r * 32))[li];
            const __half2* hp = (const __half2*)&hv;
            float2 f0 = __half22float2(hp[0]);
            float2 f1 = __half22float2(hp[1]);
            float2 f2 = __half22float2(hp[2]);
            float2 f3 = __half22float2(hp[3]);
            a0.x += wgt * f0.x;  a0.y += wgt * f0.y;
            a0.z += wgt * f1.x;  a0.w += wgt * f1.y;
            a1.x += wgt * f2.x;  a1.y += wgt * f2.y;
            a1.z += wgt * f3.x;  a1.w += wgt * f3.y;
        }
    }

    // cross-group reduction: groups hold partials of the SAME dims
    #pragma unroll
    for (int off = 8; off <= 16; off <<= 1) {
        a0.x += __shfl_xor_sync(0xffffffffu, a0.x, off);
        a0.y += __shfl_xor_sync(0xffffffffu, a0.y, off);
        a0.z += __shfl_xor_sync(0xffffffffu, a0.z, off);
        a0.w += __shfl_xor_sync(0xffffffffu, a0.w, off);
        a1.x += __shfl_xor_sync(0xffffffffu, a1.x, off);
        a1.y += __shfl_xor_sync(0xffffffffu, a1.y, off);
        a1.z += __shfl_xor_sync(0xffffffffu, a1.z, off);
        a1.w += __shfl_xor_sync(0xffffffffu, a1.w, off);
    }

    if (grp != 0) return;   // lanes 0..7 hold the full result

    if (!last) {
        __half2 o0 = __float22half2_rn(make_float2(a0.x, a0.y));
        __half2 o1 = __float22half2_rn(make_float2(a0.z, a0.w));
        __half2 o2 = __float22half2_rn(make_float2(a1.x, a1.y));
        __half2 o3 = __float22half2_rn(make_float2(a1.z, a1.w));
        int4 v;
        v.x = *(const int*)&o0;  v.y = *(const int*)&o1;
        v.z = *(const int*)&o2;  v.w = *(const int*)&o3;
        ((int4*)(hbuf(so) + (size_t)n * 32))[li] = v;
    } else {
        int4 h0v = ((const int4*)(g_h0 + (size_t)n * 32))[li];
        int4 h1v = ((const int4*)(g_h1 + (size_t)n * 32))[li];
        int4 h2v = ((const int4*)(xin  + (size_t)n * 32))[li];  // xin == g_h2
        const __half2* p0 = (const __half2*)&h0v;
        const __half2* p1 = (const __half2*)&h1v;
        const __half2* p2 = (const __half2*)&h2v;
        float f[8] = {a0.x, a0.y, a0.z, a0.w, a1.x, a1.y, a1.z, a1.w};
        #pragma unroll
        for (int q = 0; q < 4; q++) {
            float2 x0 = __half22float2(p0[q]);
            float2 x1 = __half22float2(p1[q]);
            float2 x2 = __half22float2(p2[q]);
            f[2*q]   = (x0.x + x1.x + x2.x + f[2*q])   * 0.25f;
            f[2*q+1] = (x0.y + x1.y + x2.y + f[2*q+1]) * 0.25f;
        }
        float ss = 0.f;
        #pragma unroll
        for (int q = 0; q < 8; q++) ss += f[q] * f[q];
        #pragma unroll
        for (int off = 1; off <= 4; off <<= 1)
            ss += __shfl_xor_sync(0x000000FFu, ss, off);
        float inv = 1.0f / fmaxf(sqrtf(ss), 1e-12f);
        float4 w0 = make_float4(f[0]*inv, f[1]*inv, f[2]*inv, f[3]*inv);
        float4 w1 = make_float4(f[4]*inv, f[5]*inv, f[6]*inv, f[7]*inv);
        float4* orow = (float4*)(out + (size_t)n * 32);
        orow[li * 2]     = w0;
        orow[li * 2 + 1] = w1;
    }
}

// ---------------- launch -----------------------------------------------------

extern "C" void kernel_launch(void* const* d_in, const int* in_sizes, int n_in,
                              void* d_out, int out_size) {
    const int*   batch_nodes = (const int*)  d_in[0];
    const int*   edge_index  = (const int*)  d_in[1];   // [2, E] row-major
    const float* edge_w      = (const float*)d_in[2];
    const float* user_w      = (const float*)d_in[3];
    const float* artist_w    = (const float*)d_in[4];
    const float* album_w     = (const float*)d_in[5];
    const float* audio       = (const float*)d_in[6];
    const int*   artist_ids  = (const int*)  d_in[7];
    const int*   album_ids   = (const int*)  d_in[8];
    const float* proj_w      = (const float*)d_in[9];
    const float* proj_b      = (const float*)d_in[10];
    float2*      out         = (float2*)d_out;

    const int nn = in_sizes[0];
    const int ee = in_sizes[2];
    const int* row = edge_index;
    const int* col = edge_index + (in_sizes[1] - ee);

    // zero counters with a single memset node (not a kernel launch)
    void* bp = nullptr;
    cudaGetSymbolAddress(&bp, g_blob);
    cudaMemsetAsync(bp, 0, (size_t)(3 * nn + 1) * sizeof(int));

    k_edge_stats<<<(ee + 255) / 256, 256>>>(row, col, edge_w, ee, nn);
    k_assign    <<<(nn + 1023) / 1024, 1024>>>(nn);

    const int sb = (ee + nn + 255) / 256;
    k_build<<<sb + 1024, 256>>>(row, col, edge_w, batch_nodes,
                                user_w, artist_w, album_w, audio,
                                artist_ids, album_ids, proj_w, proj_b,
                                ee, nn, sb);

    const int prop_blocks = (nn * 32 + 255) / 256;   // one warp per node
    k_prop<<<prop_blocks, 256>>>(0, 1, 0, nn, out);  // h0 -> h1   (profiled)
    k_prop<<<prop_blocks, 256>>>(1, 2, 0, nn, out);  // h1 -> h2
    k_prop<<<prop_blocks, 256>>>(2, 0, 1, nn, out);  // h2 -> out (fused final)
}

// round 7
// speedup vs baseline: 1.2095x; 1.0727x over previous
#include <cuda_runtime.h>
#include <cuda_fp16.h>
#include <math.h>

#define NUSERS 500000
#define MAXN   262144
#define MAXE   4194304
#define MAXEN  (MAXE + MAXN)

// ---------------- scratch (device globals; no allocation allowed) ------------
__device__ __half2 g_h0 [MAXN * 32];   // features: row n = 64 halfs (128B)
__device__ __half2 g_h1 [MAXN * 32];
__device__ __half2 g_h2 [MAXN * 32];
__device__ float   g_dinv [MAXN];
__device__ float   g_loopw[MAXN];
__device__ int     g_s   [MAXN];
__device__ int     g_e   [MAXN];
__device__ int     g_cur [MAXN];
__device__ unsigned long long g_dc[MAXN];  // packed: cnt<<44 | deg*2^20
__device__ int     g_hl  [MAXN + 1];       // hasloop[nn] + total
__device__ int2    g_edge[MAXEN];          // (src, half2{w,w} bits)

__device__ __forceinline__ __half2* hbuf(int i) {
    return (i == 0) ? g_h0 : ((i == 1) ? g_h1 : g_h2);
}

// ---------------- kernels ----------------------------------------------------

// merged: blocks [0, sb) do edge stats; blocks [sb, sb+1024) build features.
// The two roles are independent (stats: edges; feat: raw inputs only).
__global__ void k_stats_feat(const int* __restrict__ row,
                             const int* __restrict__ col,
                             const float* __restrict__ w,
                             const int* __restrict__ batch_nodes,
                             const float* __restrict__ user_w,
                             const float* __restrict__ artist_w,
                             const float* __restrict__ album_w,
                             const float* __restrict__ audio,
                             const int* __restrict__ artist_ids,
                             const int* __restrict__ album_ids,
                             const float* __restrict__ proj_w,
                             const float* __restrict__ proj_b,
                             int ee, int nn, int sb) {
    __shared__ float Wsh[128 * 64];       // 32 KB; used by feat role only

    if (blockIdx.x < sb) {
        // ----- edge stats role: packed deg+cnt atomic -----
        int e = blockIdx.x * blockDim.x + threadIdx.x;
        if (e >= ee) return;
        int r = row[e], c = col[e];
        if (r == c) g_hl[r] = 1;
        unsigned long long add =
            (1ULL << 44) | (unsigned long long)__float2ull_rn(w[e] * 1048576.0f);
        atomicAdd(&g_dc[c], add);
        return;
    }

    // ----- feature role -----
    int fbid = blockIdx.x - sb;
    for (int i = threadIdx.x; i < 128 * 64; i += blockDim.x)
        Wsh[i] = proj_w[i];
    __syncthreads();

    int wid  = threadIdx.x >> 5;
    int lane = threadIdx.x & 31;
    const float2* user2   = (const float2*)user_w;
    const float2* audio2  = (const float2*)audio;
    const float2* artist2 = (const float2*)artist_w;
    const float2* album2  = (const float2*)album_w;
    const float2* pb2     = (const float2*)proj_b;
    const float2* Wsh2    = (const float2*)Wsh;

    for (int n = fbid * 8 + wid; n < nn; n += 1024 * 8) {
        int bn = batch_nodes[n];
        float2 o;
        if (bn < NUSERS) {
            o = user2[(size_t)bn * 32 + lane];
        } else {
            int it  = bn - NUSERS;
            int aid = artist_ids[it];
            int bid = album_ids[it];
            float2 au = audio2[(size_t)it * 32 + lane];
            float2 ar = artist2[(size_t)aid * 32 + lane];
            float2 al = album2[(size_t)bid * 32 + lane];
            float2 me = make_float2(0.5f * (ar.x + al.x),
                                    0.5f * (ar.y + al.y));
            float2 s = pb2[lane];
            #pragma unroll
            for (int k = 0; k < 64; k++) {
                float iv = __shfl_sync(0xffffffffu, (k & 1) ? au.y : au.x, k >> 1);
                float2 wv = Wsh2[k * 32 + lane];
                s.x += iv * wv.x;
                s.y += iv * wv.y;
            }
            #pragma unroll
            for (int k = 0; k < 64; k++) {
                float iv = __shfl_sync(0xffffffffu, (k & 1) ? me.y : me.x, k >> 1);
                float2 wv = Wsh2[(64 + k) * 32 + lane];
                s.x += iv * wv.x;
                s.y += iv * wv.y;
            }
            o = s;
        }
        float ss = o.x * o.x + o.y * o.y;
        #pragma unroll
        for (int off = 16; off; off >>= 1)
            ss += __shfl_xor_sync(0xffffffffu, ss, off);
        float inv = 1.0f / fmaxf(sqrtf(ss), 1e-12f);
        o.x *= inv; o.y *= inv;
        g_h0[(size_t)n * 32 + lane] = __float22half2_rn(o);
    }
}

// finalize (loopw/dinv from packed deg+cnt) + CSR region assignment:
// per-block inclusive scan + one atomic for the block base.
__global__ void k_assign(int nn) {
    __shared__ int sh[1024];
    __shared__ int base;
    int t = threadIdx.x;
    int i = blockIdx.x * 1024 + t;
    int c = 0;
    if (i < nn) {
        unsigned long long v = g_dc[i];
        float deg = (float)(v & ((1ULL << 44) - 1)) * (1.0f / 1048576.0f);
        int   cnt = (int)(v >> 44);
        float lw = g_hl[i] ? 0.f : 1.f;
        g_loopw[i] = lw;
        float d = deg + lw;
        g_dinv[i] = (d > 0.f) ? rsqrtf(fmaxf(d, 1e-12f)) : 0.f;
        c = cnt + 1;                      // + appended self loop
    }
    sh[t] = c;
    __syncthreads();
    for (int off = 1; off < 1024; off <<= 1) {
        int v = (t >= off) ? sh[t - off] : 0;
        __syncthreads();
        sh[t] += v;
        __syncthreads();
    }
    if (t == 1023) base = atomicAdd(&g_hl[nn], sh[1023]);
    __syncthreads();
    if (i < nn) {
        int start = base + sh[t] - c;
        g_s[i]   = start;
        g_e[i]   = start + c;
        g_cur[i] = start;
    }
}

// scatter edges (and self loops) into CSR slots; weight packed as half2{w,w}.
__global__ void k_scatter(const int* __restrict__ row,
                          const int* __restrict__ col,
                          const float* __restrict__ w, int ee, int nn) {
    int e = blockIdx.x * blockDim.x + threadIdx.x;
    if (e >= ee + nn) return;
    float nm;
    int r, tgt;
    if (e < ee) {
        r = row[e]; tgt = col[e];
        nm = g_dinv[r] * w[e] * g_dinv[tgt];
    } else {
        r = tgt = e - ee;
        float dv = g_dinv[r];
        nm = dv * dv * g_loopw[r];
    }
    int p = atomicAdd(&g_cur[tgt], 1);
    __half2 wh = __half2half2(__float2half_rn(nm));
    g_edge[p] = make_int2(r, *(const int*)&wh);
}

// propagation layer v3: warp per node; 4 edge-groups of 8 lanes; each lane
// gathers 16B (8 fp16 dims) per edge. Inner loop is pure HFMA2 (half2 weight
// pre-packed in the edge record, zero converts); half2 partials flushed to
// fp32 once per 32-edge batch. Cross-group shfl reduce; last layer fuses the
// final l2norm((x0+x1+x2+x3)/4) and writes d_out.
__global__ void k_prop(int si, int so, int last, int nn,
                       float2* __restrict__ out) {
    const __half2* __restrict__ xin = hbuf(si);
    int g = blockIdx.x * blockDim.x + threadIdx.x;
    int n = g >> 5;
    if (n >= nn) return;
    int lane = threadIdx.x & 31;
    int grp  = lane >> 3;     // edge group 0..3
    int li   = lane & 7;      // lane within group (covers dims 8li..8li+7)

    int s = g_s[n];
    int e = g_e[n];
    float sf[8] = {0.f, 0.f, 0.f, 0.f, 0.f, 0.f, 0.f, 0.f};

    for (int base = s; base < e; base += 32) {
        int cnt = e - base; if (cnt > 32) cnt = 32;
        int2 ed = make_int2(0, 0);
        if (lane < cnt) ed = g_edge[base + lane];
        __half2 acc0 = __float2half2_rn(0.f);
        __half2 acc1 = acc0, acc2 = acc0, acc3 = acc0;
        int nt = (cnt + 3) >> 2;
        #pragma unroll 2
        for (int t = 0; t < nt; t++) {
            int src = t * 4 + grp;
            int   r  = __shfl_sync(0xffffffffu, ed.x, src);
            int   wb = __shfl_sync(0xffffffffu, ed.y, src);
            __half2 wh = *(const __half2*)&wb;
            int4 hv = ((const int4*)(xin + (size_t)r * 32))[li];
            const __half2* hp = (const __half2*)&hv;
            acc0 = __hfma2(hp[0], wh, acc0);
            acc1 = __hfma2(hp[1], wh, acc1);
            acc2 = __hfma2(hp[2], wh, acc2);
            acc3 = __hfma2(hp[3], wh, acc3);
        }
        float2 f0 = __half22float2(acc0);
        float2 f1 = __half22float2(acc1);
        float2 f2 = __half22float2(acc2);
        float2 f3 = __half22float2(acc3);
        sf[0] += f0.x; sf[1] += f0.y; sf[2] += f1.x; sf[3] += f1.y;
        sf[4] += f2.x; sf[5] += f2.y; sf[6] += f3.x; sf[7] += f3.y;
    }

    // cross-group reduction: groups hold partials of the SAME dims
    #pragma unroll
    for (int off = 8; off <= 16; off <<= 1) {
        #pragma unroll
        for (int q = 0; q < 8; q++)
            sf[q] += __shfl_xor_sync(0xffffffffu, sf[q], off);
    }

    if (grp != 0) return;   // lanes 0..7 hold the full result

    if (!last) {
        __half2 o0 = __float22half2_rn(make_float2(sf[0], sf[1]));
        __half2 o1 = __float22half2_rn(make_float2(sf[2], sf[3]));
        __half2 o2 = __float22half2_rn(make_float2(sf[4], sf[5]));
        __half2 o3 = __float22half2_rn(make_float2(sf[6], sf[7]));
        int4 v;
        v.x = *(const int*)&o0;  v.y = *(const int*)&o1;
        v.z = *(const int*)&o2;  v.w = *(const int*)&o3;
        ((int4*)(hbuf(so) + (size_t)n * 32))[li] = v;
    } else {
        int4 h0v = ((const int4*)(g_h0 + (size_t)n * 32))[li];
        int4 h1v = ((const int4*)(g_h1 + (size_t)n * 32))[li];
        int4 h2v = ((const int4*)(xin  + (size_t)n * 32))[li];  // xin == g_h2
        const __half2* p0 = (const __half2*)&h0v;
        const __half2* p1 = (const __half2*)&h1v;
        const __half2* p2 = (const __half2*)&h2v;
        #pragma unroll
        for (int q = 0; q < 4; q++) {
            float2 x0 = __half22float2(p0[q]);
            float2 x1 = __half22float2(p1[q]);
            float2 x2 = __half22float2(p2[q]);
            sf[2*q]   = (x0.x + x1.x + x2.x + sf[2*q])   * 0.25f;
            sf[2*q+1] = (x0.y + x1.y + x2.y + sf[2*q+1]) * 0.25f;
        }
        float ss = 0.f;
        #pragma unroll
        for (int q = 0; q < 8; q++) ss += sf[q] * sf[q];
        #pragma unroll
        for (int off = 1; off <= 4; off <<= 1)
            ss += __shfl_xor_sync(0x000000FFu, ss, off);
        float inv = 1.0f / fmaxf(sqrtf(ss), 1e-12f);
        float4 w0 = make_float4(sf[0]*inv, sf[1]*inv, sf[2]*inv, sf[3]*inv);
        float4 w1 = make_float4(sf[4]*inv, sf[5]*inv, sf[6]*inv, sf[7]*inv);
        float4* orow = (float4*)(out + (size_t)n * 32);
        orow[li * 2]     = w0;
        orow[li * 2 + 1] = w1;
    }
}

// ---------------- launch -----------------------------------------------------

extern "C" void kernel_launch(void* const* d_in, const int* in_sizes, int n_in,
                              void* d_out, int out_size) {
    const int*   batch_nodes = (const int*)  d_in[0];
    const int*   edge_index  = (const int*)  d_in[1];   // [2, E] row-major
    const float* edge_w      = (const float*)d_in[2];
    const float* user_w      = (const float*)d_in[3];
    const float* artist_w    = (const float*)d_in[4];
    const float* album_w     = (const float*)d_in[5];
    const float* audio       = (const float*)d_in[6];
    const int*   artist_ids  = (const int*)  d_in[7];
    const int*   album_ids   = (const int*)  d_in[8];
    const float* proj_w      = (const float*)d_in[9];
    const float* proj_b      = (const float*)d_in[10];
    float2*      out         = (float2*)d_out;

    const int nn = in_sizes[0];
    const int ee = in_sizes[2];
    const int* row = edge_index;
    const int* col = edge_index + (in_sizes[1] - ee);

    // zero counters with memset nodes (not kernel launches)
    void* p1 = nullptr; void* p2 = nullptr;
    cudaGetSymbolAddress(&p1, g_dc);
    cudaGetSymbolAddress(&p2, g_hl);
    cudaMemsetAsync(p1, 0, (size_t)nn * sizeof(unsigned long long));
    cudaMemsetAsync(p2, 0, (size_t)(nn + 1) * sizeof(int));

    const int sb = (ee + 255) / 256;
    k_stats_feat<<<sb + 1024, 256>>>(row, col, edge_w, batch_nodes,
                                     user_w, artist_w, album_w, audio,
                                     artist_ids, album_ids, proj_w, proj_b,
                                     ee, nn, sb);
    k_assign <<<(nn + 1023) / 1024, 1024>>>(nn);
    k_scatter<<<(ee + nn + 255) / 256, 256>>>(row, col, edge_w, ee, nn);

    const int prop_blocks = (nn * 32 + 255) / 256;   // one warp per node
    k_prop<<<prop_blocks, 256>>>(0, 1, 0, nn, out);  // h0 -> h1   (profiled slot)
    k_prop<<<prop_blocks, 256>>>(1, 2, 0, nn, out);  // h1 -> h2
    k_prop<<<prop_blocks, 256>>>(2, 0, 1, nn, out);  // h2 -> out (fused final)
}